// round 5
// baseline (speedup 1.0000x reference)
#include <cuda_runtime.h>
#include <math.h>
#include <stdint.h>

#define NN 50000
#define EE 800000
#define INF_F 128
#define OUTF 64
#define HH 4
#define DD 16

// ---------------- device scratch (no allocations allowed) ----------------
__device__ float g_q[NN * OUTF];
__device__ float g_k[NN * OUTF];
__device__ float g_v[NN * OUTF];
__device__ float g_qq[NN * HH];
__device__ float g_kk[NN * HH];
__device__ int   g_cnt[NN];
__device__ int   g_rs[NN];
__device__ int   g_cur[NN];
__device__ int   g_csr[EE];
__device__ int   g_is64;
__device__ int   g_total;

// packed f32x2 FMA: d = a*b + c elementwise on packed pairs (Blackwell FFMA2)
__device__ __forceinline__ unsigned long long ffma2(
    unsigned long long a, unsigned long long b, unsigned long long c)
{
    unsigned long long d;
    asm("fma.rn.f32x2 %0, %1, %2, %3;" : "=l"(d) : "l"(a), "l"(b), "l"(c));
    return d;
}

__device__ __forceinline__ float unpack_sum(unsigned long long a) {
    float lo = __uint_as_float((unsigned)(a & 0xffffffffu));
    float hi = __uint_as_float((unsigned)(a >> 32));
    return lo + hi;
}

// ---------------- fused QKV projection + prep + Minkowski self-products ---
// block = 192 threads (thread = one output column among q|k|v), tile = 8 rows.
// Inner product accumulated as packed f32x2 pairs along K (FFMA2, 2x rate).
// Also zeroes the CSR histogram, resets g_total, and detects the edge_index
// dtype (int64 vs int32: reading int32 data as int64 packs two indices into
// one word -> out-of-range with overwhelming probability over 1024 words).
__global__ __launch_bounds__(192) void qkv_kernel(
    const float* __restrict__ x,
    const float* __restrict__ Wq, const float* __restrict__ bq,
    const float* __restrict__ Wk, const float* __restrict__ bk,
    const float* __restrict__ Wv, const float* __restrict__ bv,
    const void* __restrict__ ei)
{
    __shared__ __align__(16) float xs[8 * 128];
    int tid = threadIdx.x;
    int tile = blockIdx.x;                  // 6250 tiles * 8 rows = 50000 exactly

    // ---- fused prep ----
    int gi = tile * 192 + tid;
    if (gi < NN) g_cnt[gi] = 0;
    if (gi == 0) g_total = 0;
    if (tile == 0 && tid < 32) {
        int lane = tid;
        const long long* e64 = (const long long*)ei;
        int ok = 1;
        for (int t = lane; t < 1024; t += 32) {
            long long v = e64[t];
            if (v < 0 || v >= NN) ok = 0;
        }
        unsigned b = __ballot_sync(0xffffffffu, ok);
        if (lane == 0) g_is64 = (b == 0xffffffffu) ? 1 : 0;
    }

    int sel = tid >> 6;   // 0 -> q, 1 -> k, 2 -> v
    int cc  = tid & 63;

    const float* W;
    const float* bias;
    float* out;
    if (sel == 0)      { W = Wq; bias = bq; out = g_q; }
    else if (sel == 1) { W = Wk; bias = bk; out = g_k; }
    else               { W = Wv; bias = bv; out = g_v; }

    const float4* xg4 = (const float4*)(x + (size_t)tile * 8 * 128);
    float4* xs4 = (float4*)xs;
    for (int i = tid; i < 256; i += 192) xs4[i] = xg4[i];
    __syncthreads();

    unsigned long long acc[8];
#pragma unroll
    for (int r = 0; r < 8; r++) acc[r] = 0ull;

    const ulonglong2* Wr = (const ulonglong2*)(W + cc * 128);
    const ulonglong2* xs2 = (const ulonglong2*)xs;
#pragma unroll 4
    for (int k4 = 0; k4 < 32; k4++) {
        ulonglong2 w = Wr[k4];
#pragma unroll
        for (int r = 0; r < 8; r++) {
            ulonglong2 xv = xs2[r * 32 + k4];
            acc[r] = ffma2(w.x, xv.x, acc[r]);
            acc[r] = ffma2(w.y, xv.y, acc[r]);
        }
    }

    float b = bias[cc];
    float res[8];
#pragma unroll
    for (int r = 0; r < 8; r++) res[r] = unpack_sum(acc[r]) + b;

    int row0 = tile * 8;
#pragma unroll
    for (int r = 0; r < 8; r++) out[(row0 + r) * 64 + cc] = res[r];

    // fused Minkowski self-products for q and k: reduce over the 16 lanes of
    // each head (warp lanes span 32 consecutive cc -> lane group == head chunk)
    if (sel < 2) {
        float sign = ((cc & 15) == 15) ? -1.f : 1.f;
        float* dst = (sel == 0) ? g_qq : g_kk;
        int h = cc >> 4;
#pragma unroll
        for (int r = 0; r < 8; r++) {
            float p = res[r] * res[r] * sign;
            p += __shfl_xor_sync(0xffffffffu, p, 1);
            p += __shfl_xor_sync(0xffffffffu, p, 2);
            p += __shfl_xor_sync(0xffffffffu, p, 4);
            p += __shfl_xor_sync(0xffffffffu, p, 8);
            if ((cc & 15) == 0) dst[(row0 + r) * 4 + h] = p;
        }
    }
}

// ---------------- CSR build ----------------
// histogram: 2 edges per thread, vectorized index loads
__global__ void hist_kernel(const void* ei) {
    int is64 = g_is64;
    int t = blockIdx.x * blockDim.x + threadIdx.x;
    if (t >= EE / 2) return;
    int d0, d1;
    if (is64) {
        longlong2 d = ((const longlong2*)((const long long*)ei + EE))[t];
        d0 = (int)d.x; d1 = (int)d.y;
    } else {
        int2 d = ((const int2*)((const int*)ei + EE))[t];
        d0 = d.x; d1 = d.y;
    }
    atomicAdd(&g_cnt[d0], 1);
    atomicAdd(&g_cnt[d1], 1);
}

// range allocation: order-free replacement for a prefix scan. Each node gets
// a contiguous chunk [off, off+cnt) via one aggregated atomic (REDUX.SUM).
__global__ void alloc_kernel() {
    int i = blockIdx.x * blockDim.x + threadIdx.x;
    if (i >= NN) return;
    int c = g_cnt[i];
    int off = atomicAdd(&g_total, c);
    g_rs[i] = off;
    g_cur[i] = off;
}

// scatter: 2 edges per thread, vectorized index loads
__global__ void scatter_kernel(const void* ei) {
    int is64 = g_is64;
    int t = blockIdx.x * blockDim.x + threadIdx.x;
    if (t >= EE / 2) return;
    int s0, s1, d0, d1;
    if (is64) {
        const long long* e = (const long long*)ei;
        longlong2 sv = ((const longlong2*)e)[t];
        longlong2 dv = ((const longlong2*)(e + EE))[t];
        s0 = (int)sv.x; s1 = (int)sv.y;
        d0 = (int)dv.x; d1 = (int)dv.y;
    } else {
        const int* e = (const int*)ei;
        int2 sv = ((const int2*)e)[t];
        int2 dv = ((const int2*)(e + EE))[t];
        s0 = sv.x; s1 = sv.y;
        d0 = dv.x; d1 = dv.y;
    }
    g_csr[atomicAdd(&g_cur[d0], 1)] = s0;
    g_csr[atomicAdd(&g_cur[d1], 1)] = s1;
}

// ---------------- fused gather attention + output projection ----------------
// One warp per dst node. lane l owns flat dims {2l, 2l+1}; head h = l/8; 8-lane
// groups reduce Minkowski dots via shfl. <q,q>,<k,k> precomputed per node.
// exp(-acosh(arg)) == 1/(arg + sqrt(arg^2-1))  -> no MUFU log/exp.
// Softmax denom cancels exactly into the L2 norm: att = S / (||S|| + EPS*s),
// and the max-shift cancels too (scale invariance), so no online max needed.
// Epilogue: out = att @ Wo^T + bo in-warp via smem staging (Wo L1-resident).
__global__ __launch_bounds__(256) void attn_out_kernel(
    const float* __restrict__ Wo, const float* __restrict__ bo,
    float* __restrict__ outp)
{
    __shared__ __align__(16) float satt[8][64];
    int gtid = blockIdx.x * blockDim.x + threadIdx.x;
    int i = gtid >> 5;
    if (i >= NN) return;
    int w = threadIdx.x >> 5;
    int lane = threadIdx.x & 31;
    int h  = lane >> 3;
    int dp = lane & 7;

    float2 kv = *(const float2*)(g_k + i * 64 + 2 * lane);
    float sign = (dp == 7) ? -1.f : 1.f;   // flat dim 15 carries Minkowski minus
    float kkv = g_kk[i * 4 + h];

    int js = g_rs[i];
    int je = js + g_cnt[i];

    float s = 0.f, a0 = 0.f, a1 = 0.f;
    const float CLMP = (1.0f + 1e-6f) * (1.0f + 1e-6f);

    int j = js;
    for (; j + 3 < je; j += 4) {
        int s0 = g_csr[j];
        int s1 = g_csr[j + 1];
        int s2 = g_csr[j + 2];
        int s3 = g_csr[j + 3];
        float2 q0 = *(const float2*)(g_q + s0 * 64 + 2 * lane);
        float2 q1 = *(const float2*)(g_q + s1 * 64 + 2 * lane);
        float2 q2 = *(const float2*)(g_q + s2 * 64 + 2 * lane);
        float2 q3 = *(const float2*)(g_q + s3 * 64 + 2 * lane);
        float2 v0 = *(const float2*)(g_v + s0 * 64 + 2 * lane);
        float2 v1 = *(const float2*)(g_v + s1 * 64 + 2 * lane);
        float2 v2 = *(const float2*)(g_v + s2 * 64 + 2 * lane);
        float2 v3 = *(const float2*)(g_v + s3 * 64 + 2 * lane);
        float qq0 = g_qq[s0 * 4 + h];
        float qq1 = g_qq[s1 * 4 + h];
        float qq2 = g_qq[s2 * 4 + h];
        float qq3 = g_qq[s3 * 4 + h];

        float d0 = fmaf(q0.x, kv.x, sign * q0.y * kv.y);
        float d1 = fmaf(q1.x, kv.x, sign * q1.y * kv.y);
        float d2 = fmaf(q2.x, kv.x, sign * q2.y * kv.y);
        float d3 = fmaf(q3.x, kv.x, sign * q3.y * kv.y);
#pragma unroll
        for (int o = 1; o <= 4; o <<= 1) {
            d0 += __shfl_xor_sync(0xffffffffu, d0, o);
            d1 += __shfl_xor_sync(0xffffffffu, d1, o);
            d2 += __shfl_xor_sync(0xffffffffu, d2, o);
            d3 += __shfl_xor_sync(0xffffffffu, d3, o);
        }

        float r0 = __fdividef(d0 * d0, fmaxf(fabsf(qq0 * kkv), 1e-9f)) + 1e-9f;
        float r1 = __fdividef(d1 * d1, fmaxf(fabsf(qq1 * kkv), 1e-9f)) + 1e-9f;
        float r2 = __fdividef(d2 * d2, fmaxf(fabsf(qq2 * kkv), 1e-9f)) + 1e-9f;
        float r3 = __fdividef(d3 * d3, fmaxf(fabsf(qq3 * kkv), 1e-9f)) + 1e-9f;
        r0 = fmaxf(r0, CLMP);
        r1 = fmaxf(r1, CLMP);
        r2 = fmaxf(r2, CLMP);
        r3 = fmaxf(r3, CLMP);
        float p0 = __frcp_rn(sqrtf(r0) + sqrtf(r0 - 1.0f));
        float p1 = __frcp_rn(sqrtf(r1) + sqrtf(r1 - 1.0f));
        float p2 = __frcp_rn(sqrtf(r2) + sqrtf(r2 - 1.0f));
        float p3 = __frcp_rn(sqrtf(r3) + sqrtf(r3 - 1.0f));

        s += (p0 + p1) + (p2 + p3);
        a0 = fmaf(p0, v0.x, fmaf(p1, v1.x, fmaf(p2, v2.x, fmaf(p3, v3.x, a0))));
        a1 = fmaf(p0, v0.y, fmaf(p1, v1.y, fmaf(p2, v2.y, fmaf(p3, v3.y, a1))));
    }
    for (; j < je; j++) {
        int s0 = g_csr[j];
        float2 q0 = *(const float2*)(g_q + s0 * 64 + 2 * lane);
        float2 v0 = *(const float2*)(g_v + s0 * 64 + 2 * lane);
        float qq0 = g_qq[s0 * 4 + h];
        float d0 = fmaf(q0.x, kv.x, sign * q0.y * kv.y);
        d0 += __shfl_xor_sync(0xffffffffu, d0, 1);
        d0 += __shfl_xor_sync(0xffffffffu, d0, 2);
        d0 += __shfl_xor_sync(0xffffffffu, d0, 4);
        float r0 = __fdividef(d0 * d0, fmaxf(fabsf(qq0 * kkv), 1e-9f)) + 1e-9f;
        r0 = fmaxf(r0, CLMP);
        float p0 = __frcp_rn(sqrtf(r0) + sqrtf(r0 - 1.0f));
        s += p0;
        a0 = fmaf(p0, v0.x, a0);
        a1 = fmaf(p0, v0.y, a1);
    }

    float nsq = fmaf(a0, a0, a1 * a1);
    nsq += __shfl_xor_sync(0xffffffffu, nsq, 1);
    nsq += __shfl_xor_sync(0xffffffffu, nsq, 2);
    nsq += __shfl_xor_sync(0xffffffffu, nsq, 4);
    float norm = sqrtf(nsq);
    // agg = S/s, attended = agg/(||agg||+EPS) = S/(||S|| + EPS*s); 0 if no mass
    float scale = (norm > 0.f) ? __frcp_rn(norm + 1e-9f * s) : 0.f;
    satt[w][2 * lane]     = a0 * scale;
    satt[w][2 * lane + 1] = a1 * scale;
    __syncwarp();

    // out[i, :] = attended @ Wo^T + bo ; lane handles cols 2*lane, 2*lane+1
    int c0 = 2 * lane;
    unsigned long long acc0 = 0ull, acc1 = 0ull;
    const ulonglong2* a2  = (const ulonglong2*)satt[w];
    const ulonglong2* w02 = (const ulonglong2*)(Wo + c0 * 64);
    const ulonglong2* w12 = (const ulonglong2*)(Wo + (c0 + 1) * 64);
#pragma unroll
    for (int t = 0; t < 16; t++) {
        ulonglong2 a = a2[t];
        ulonglong2 xw = w02[t];
        ulonglong2 yw = w12[t];
        acc0 = ffma2(a.x, xw.x, acc0);
        acc0 = ffma2(a.y, xw.y, acc0);
        acc1 = ffma2(a.x, yw.x, acc1);
        acc1 = ffma2(a.y, yw.y, acc1);
    }
    float2 bv2 = *(const float2*)(bo + c0);
    float2 res;
    res.x = unpack_sum(acc0) + bv2.x;
    res.y = unpack_sum(acc1) + bv2.y;
    *(float2*)(outp + i * 64 + c0) = res;
}

// ---------------- launch (single stream, 5 kernels) --------------------------
extern "C" void kernel_launch(void* const* d_in, const int* in_sizes, int n_in,
                              void* d_out, int out_size) {
    const float* x  = (const float*)d_in[0];
    const void*  ei = d_in[1];
    const float* Wq = (const float*)d_in[2];
    const float* bq = (const float*)d_in[3];
    const float* Wk = (const float*)d_in[4];
    const float* bk = (const float*)d_in[5];
    const float* Wv = (const float*)d_in[6];
    const float* bv = (const float*)d_in[7];
    const float* Wo = (const float*)d_in[8];
    const float* bo = (const float*)d_in[9];
    float* out = (float*)d_out;

    qkv_kernel<<<NN / 8, 192>>>(x, Wq, bq, Wk, bk, Wv, bv, ei);
    hist_kernel<<<(EE / 2 + 255) / 256, 256>>>(ei);
    alloc_kernel<<<(NN + 255) / 256, 256>>>();
    scatter_kernel<<<(EE / 2 + 255) / 256, 256>>>(ei);
    attn_out_kernel<<<(NN * 32) / 256, 256>>>(Wo, bo, out);
}

// round 6
// speedup vs baseline: 1.3676x; 1.3676x over previous
#include <cuda_runtime.h>
#include <math.h>
#include <stdint.h>

#define NN 50000
#define EE 800000
#define INF_F 128
#define OUTF 64
#define HH 4
#define DD 16

// ---------------- device scratch (no allocations allowed) ----------------
// Invariants maintained ACROSS calls (restored within each call):
//   g_cnt[] == 0  (zero-init at load; alloc_kernel re-zeroes after reading)
//   g_total == 0  (zero-init at load; scatter_kernel resets)
__device__ float g_q[NN * OUTF];
__device__ float g_k[NN * OUTF];
__device__ float g_v[NN * OUTF];
__device__ float g_att[NN * OUTF];
__device__ float g_qq[NN * HH];
__device__ float g_kk[NN * HH];
__device__ int   g_cnt[NN];
__device__ int   g_rs[NN];
__device__ int   g_cur[NN];
__device__ int   g_csr[EE];
__device__ int   g_is64;
__device__ int   g_total;

// packed f32x2 FMA: d = a*b + c elementwise on packed pairs (Blackwell FFMA2)
__device__ __forceinline__ unsigned long long ffma2(
    unsigned long long a, unsigned long long b, unsigned long long c)
{
    unsigned long long d;
    asm("fma.rn.f32x2 %0, %1, %2, %3;" : "=l"(d) : "l"(a), "l"(b), "l"(c));
    return d;
}

__device__ __forceinline__ float unpack_sum(unsigned long long a) {
    float lo = __uint_as_float((unsigned)(a & 0xffffffffu));
    float hi = __uint_as_float((unsigned)(a >> 32));
    return lo + hi;
}

// ---------------- fused QKV projection + edge histogram + self-products ---
// block = 192 threads (thread = one output column among q|k|v), tile = 8 rows.
// Inner product accumulated as packed f32x2 pairs along K (FFMA2, 2x rate).
// Each block also histograms its 128 edges (6250 * 128 = 800000 exactly).
// edge_index dtype detected per block (int64 vs int32: reading int32 data as
// int64 packs two indices into one word -> out-of-range w.h.p.).
__global__ __launch_bounds__(192) void qkv_kernel(
    const float* __restrict__ x,
    const float* __restrict__ Wq, const float* __restrict__ bq,
    const float* __restrict__ Wk, const float* __restrict__ bk,
    const float* __restrict__ Wv, const float* __restrict__ bv,
    const void* __restrict__ ei)
{
    __shared__ __align__(16) float xs[8 * 128];
    __shared__ int s_is64;
    int tid = threadIdx.x;
    int tile = blockIdx.x;                  // 6250 tiles * 8 rows = 50000 exactly

    // ---- per-block dtype detection (also publish globally for scatter) ----
    if (tid < 32) {
        const long long* e64 = (const long long*)ei;
        int ok = 1;
        for (int t = tid; t < 1024; t += 32) {
            long long v = e64[t];
            if (v < 0 || v >= NN) ok = 0;
        }
        unsigned b = __ballot_sync(0xffffffffu, ok);
        if (tid == 0) {
            int f = (b == 0xffffffffu) ? 1 : 0;
            s_is64 = f;
            if (tile == 0) g_is64 = f;
        }
    }

    // ---- stage x tile ----
    const float4* xg4 = (const float4*)(x + (size_t)tile * 8 * 128);
    float4* xs4 = (float4*)xs;
    for (int i = tid; i < 256; i += 192) xs4[i] = xg4[i];
    __syncthreads();

    // ---- fused histogram: this block's 128 edges (g_cnt starts all-zero) ----
    if (tid < 128) {
        long long e = (long long)tile * 128 + tid;
        int dst = s_is64 ? (int)((const long long*)ei)[EE + e]
                         : ((const int*)ei)[EE + e];
        atomicAdd(&g_cnt[dst], 1);
    }

    int sel = tid >> 6;   // 0 -> q, 1 -> k, 2 -> v
    int cc  = tid & 63;

    const float* W;
    const float* bias;
    float* out;
    if (sel == 0)      { W = Wq; bias = bq; out = g_q; }
    else if (sel == 1) { W = Wk; bias = bk; out = g_k; }
    else               { W = Wv; bias = bv; out = g_v; }

    unsigned long long acc[8];
#pragma unroll
    for (int r = 0; r < 8; r++) acc[r] = 0ull;

    const ulonglong2* Wr = (const ulonglong2*)(W + cc * 128);
    const ulonglong2* xs2 = (const ulonglong2*)xs;
#pragma unroll 4
    for (int k4 = 0; k4 < 32; k4++) {
        ulonglong2 w = Wr[k4];
#pragma unroll
        for (int r = 0; r < 8; r++) {
            ulonglong2 xv = xs2[r * 32 + k4];
            acc[r] = ffma2(w.x, xv.x, acc[r]);
            acc[r] = ffma2(w.y, xv.y, acc[r]);
        }
    }

    float b = bias[cc];
    float res[8];
#pragma unroll
    for (int r = 0; r < 8; r++) res[r] = unpack_sum(acc[r]) + b;

    int row0 = tile * 8;
#pragma unroll
    for (int r = 0; r < 8; r++) out[(row0 + r) * 64 + cc] = res[r];

    // fused Minkowski self-products for q and k: reduce over the 16 lanes of
    // each head (warp lanes span 32 consecutive cc -> lane group == head chunk)
    if (sel < 2) {
        float sign = ((cc & 15) == 15) ? -1.f : 1.f;
        float* dst = (sel == 0) ? g_qq : g_kk;
        int h = cc >> 4;
#pragma unroll
        for (int r = 0; r < 8; r++) {
            float p = res[r] * res[r] * sign;
            p += __shfl_xor_sync(0xffffffffu, p, 1);
            p += __shfl_xor_sync(0xffffffffu, p, 2);
            p += __shfl_xor_sync(0xffffffffu, p, 4);
            p += __shfl_xor_sync(0xffffffffu, p, 8);
            if ((cc & 15) == 0) dst[(row0 + r) * 4 + h] = p;
        }
    }
}

// range allocation: order-free replacement for a prefix scan. Each node gets
// a contiguous chunk [off, off+cnt) via one aggregated atomic (REDUX.SUM).
// Re-zeroes g_cnt after reading (restores the cross-call invariant).
__global__ void alloc_kernel() {
    int i = blockIdx.x * blockDim.x + threadIdx.x;
    if (i >= NN) return;
    int c = g_cnt[i];
    g_cnt[i] = 0;
    int off = atomicAdd(&g_total, c);
    g_rs[i] = off;
    g_cur[i] = off;
}

// scatter: 2 edges per thread, vectorized index loads. Resets g_total.
__global__ void scatter_kernel(const void* ei) {
    int is64 = g_is64;
    int t = blockIdx.x * blockDim.x + threadIdx.x;
    if (t == 0) g_total = 0;
    if (t >= EE / 2) return;
    int s0, s1, d0, d1;
    if (is64) {
        const long long* e = (const long long*)ei;
        longlong2 sv = ((const longlong2*)e)[t];
        longlong2 dv = ((const longlong2*)(e + EE))[t];
        s0 = (int)sv.x; s1 = (int)sv.y;
        d0 = (int)dv.x; d1 = (int)dv.y;
    } else {
        const int* e = (const int*)ei;
        int2 sv = ((const int2*)e)[t];
        int2 dv = ((const int2*)(e + EE))[t];
        s0 = sv.x; s1 = sv.y;
        d0 = dv.x; d1 = dv.y;
    }
    g_csr[atomicAdd(&g_cur[d0], 1)] = s0;
    g_csr[atomicAdd(&g_cur[d1], 1)] = s1;
}

// ---------------- gather attention: one warp per dst node --------------------
// lane l owns flat dims {2l, 2l+1}; head h = l/8; 8-lane groups reduce dots.
// After scatter, g_cur[i] == row_end, so [g_rs[i], g_cur[i]) is the edge range.
// exp(-acosh(arg)) == 1/(arg + sqrt(arg^2-1))  -> no MUFU log/exp.
// Softmax denom cancels exactly into the L2 norm: att = S / (||S|| + EPS*s),
// and the max-shift cancels too (scale invariance), so no online max needed.
__global__ __launch_bounds__(256) void attn_kernel() {
    int gtid = blockIdx.x * blockDim.x + threadIdx.x;
    int i = gtid >> 5;
    if (i >= NN) return;
    int lane = threadIdx.x & 31;
    int h  = lane >> 3;
    int dp = lane & 7;

    float2 kv = *(const float2*)(g_k + i * 64 + 2 * lane);
    float sign = (dp == 7) ? -1.f : 1.f;   // flat dim 15 carries Minkowski minus
    float kkv = g_kk[i * 4 + h];

    int js = g_rs[i];
    int je = g_cur[i];

    float s = 0.f, a0 = 0.f, a1 = 0.f;
    const float CLMP = (1.0f + 1e-6f) * (1.0f + 1e-6f);

    int j = js;
    for (; j + 3 < je; j += 4) {
        int s0 = g_csr[j];
        int s1 = g_csr[j + 1];
        int s2 = g_csr[j + 2];
        int s3 = g_csr[j + 3];
        float2 q0 = *(const float2*)(g_q + s0 * 64 + 2 * lane);
        float2 q1 = *(const float2*)(g_q + s1 * 64 + 2 * lane);
        float2 q2 = *(const float2*)(g_q + s2 * 64 + 2 * lane);
        float2 q3 = *(const float2*)(g_q + s3 * 64 + 2 * lane);
        float2 v0 = *(const float2*)(g_v + s0 * 64 + 2 * lane);
        float2 v1 = *(const float2*)(g_v + s1 * 64 + 2 * lane);
        float2 v2 = *(const float2*)(g_v + s2 * 64 + 2 * lane);
        float2 v3 = *(const float2*)(g_v + s3 * 64 + 2 * lane);
        float qq0 = g_qq[s0 * 4 + h];
        float qq1 = g_qq[s1 * 4 + h];
        float qq2 = g_qq[s2 * 4 + h];
        float qq3 = g_qq[s3 * 4 + h];

        float d0 = fmaf(q0.x, kv.x, sign * q0.y * kv.y);
        float d1 = fmaf(q1.x, kv.x, sign * q1.y * kv.y);
        float d2 = fmaf(q2.x, kv.x, sign * q2.y * kv.y);
        float d3 = fmaf(q3.x, kv.x, sign * q3.y * kv.y);
#pragma unroll
        for (int o = 1; o <= 4; o <<= 1) {
            d0 += __shfl_xor_sync(0xffffffffu, d0, o);
            d1 += __shfl_xor_sync(0xffffffffu, d1, o);
            d2 += __shfl_xor_sync(0xffffffffu, d2, o);
            d3 += __shfl_xor_sync(0xffffffffu, d3, o);
        }

        float r0 = __fdividef(d0 * d0, fmaxf(fabsf(qq0 * kkv), 1e-9f)) + 1e-9f;
        float r1 = __fdividef(d1 * d1, fmaxf(fabsf(qq1 * kkv), 1e-9f)) + 1e-9f;
        float r2 = __fdividef(d2 * d2, fmaxf(fabsf(qq2 * kkv), 1e-9f)) + 1e-9f;
        float r3 = __fdividef(d3 * d3, fmaxf(fabsf(qq3 * kkv), 1e-9f)) + 1e-9f;
        r0 = fmaxf(r0, CLMP);
        r1 = fmaxf(r1, CLMP);
        r2 = fmaxf(r2, CLMP);
        r3 = fmaxf(r3, CLMP);
        float p0 = __frcp_rn(sqrtf(r0) + sqrtf(r0 - 1.0f));
        float p1 = __frcp_rn(sqrtf(r1) + sqrtf(r1 - 1.0f));
        float p2 = __frcp_rn(sqrtf(r2) + sqrtf(r2 - 1.0f));
        float p3 = __frcp_rn(sqrtf(r3) + sqrtf(r3 - 1.0f));

        s += (p0 + p1) + (p2 + p3);
        a0 = fmaf(p0, v0.x, fmaf(p1, v1.x, fmaf(p2, v2.x, fmaf(p3, v3.x, a0))));
        a1 = fmaf(p0, v0.y, fmaf(p1, v1.y, fmaf(p2, v2.y, fmaf(p3, v3.y, a1))));
    }
    for (; j < je; j++) {
        int s0 = g_csr[j];
        float2 q0 = *(const float2*)(g_q + s0 * 64 + 2 * lane);
        float2 v0 = *(const float2*)(g_v + s0 * 64 + 2 * lane);
        float qq0 = g_qq[s0 * 4 + h];
        float d0 = fmaf(q0.x, kv.x, sign * q0.y * kv.y);
        d0 += __shfl_xor_sync(0xffffffffu, d0, 1);
        d0 += __shfl_xor_sync(0xffffffffu, d0, 2);
        d0 += __shfl_xor_sync(0xffffffffu, d0, 4);
        float r0 = __fdividef(d0 * d0, fmaxf(fabsf(qq0 * kkv), 1e-9f)) + 1e-9f;
        r0 = fmaxf(r0, CLMP);
        float p0 = __frcp_rn(sqrtf(r0) + sqrtf(r0 - 1.0f));
        s += p0;
        a0 = fmaf(p0, v0.x, a0);
        a1 = fmaf(p0, v0.y, a1);
    }

    float nsq = fmaf(a0, a0, a1 * a1);
    nsq += __shfl_xor_sync(0xffffffffu, nsq, 1);
    nsq += __shfl_xor_sync(0xffffffffu, nsq, 2);
    nsq += __shfl_xor_sync(0xffffffffu, nsq, 4);
    float norm = sqrtf(nsq);
    // agg = S/s, attended = agg/(||agg||+EPS) = S/(||S|| + EPS*s); 0 if no mass
    float scale = (norm > 0.f) ? __frcp_rn(norm + 1e-9f * s) : 0.f;
    float2 o;
    o.x = a0 * scale;
    o.y = a1 * scale;
    *(float2*)(g_att + i * 64 + 2 * lane) = o;
}

// ---------------- output projection: [N,64] x [64,64]^T + bias --------------
// 256-thread blocks = 4 independent 16-row tiles (64 columns each), FFMA2.
// Wo read is amortized over 16 rows per tile (this matters: per-node Wo reads
// were the R4/R5 regression).
__global__ __launch_bounds__(256) void out_kernel(
    const float* __restrict__ Wo, const float* __restrict__ bo,
    float* __restrict__ out)
{
    __shared__ __align__(16) float as[4][16 * 64];
    int grp = threadIdx.x >> 6;     // tile within block
    int tid = threadIdx.x & 63;     // column
    int tile = blockIdx.x * 4 + grp;
    if (tile >= 3125) return;       // 3125 tiles * 16 rows = 50000

    const float4* ag = (const float4*)(g_att + (size_t)tile * 16 * 64);
    float4* as4 = (float4*)as[grp];
    for (int i = tid; i < 256; i += 64) as4[i] = ag[i];
    __syncthreads();

    unsigned long long acc[16];
#pragma unroll
    for (int r = 0; r < 16; r++) acc[r] = 0ull;

    const ulonglong2* Wr = (const ulonglong2*)(Wo + tid * 64);
    const ulonglong2* as2 = (const ulonglong2*)as[grp];
#pragma unroll 4
    for (int k4 = 0; k4 < 16; k4++) {
        ulonglong2 w = Wr[k4];
#pragma unroll
        for (int r = 0; r < 16; r++) {
            ulonglong2 a = as2[r * 16 + k4];
            acc[r] = ffma2(w.x, a.x, acc[r]);
            acc[r] = ffma2(w.y, a.y, acc[r]);
        }
    }

    float b = bo[tid];
    int row0 = tile * 16;
#pragma unroll
    for (int r = 0; r < 16; r++) out[(row0 + r) * 64 + tid] = unpack_sum(acc[r]) + b;
}

// ---------------- launch (single stream, 5 kernels; attn is launch #4) -------
extern "C" void kernel_launch(void* const* d_in, const int* in_sizes, int n_in,
                              void* d_out, int out_size) {
    const float* x  = (const float*)d_in[0];
    const void*  ei = d_in[1];
    const float* Wq = (const float*)d_in[2];
    const float* bq = (const float*)d_in[3];
    const float* Wk = (const float*)d_in[4];
    const float* bk = (const float*)d_in[5];
    const float* Wv = (const float*)d_in[6];
    const float* bv = (const float*)d_in[7];
    const float* Wo = (const float*)d_in[8];
    const float* bo = (const float*)d_in[9];
    float* out = (float*)d_out;

    qkv_kernel<<<NN / 8, 192>>>(x, Wq, bq, Wk, bk, Wv, bv, ei);
    alloc_kernel<<<(NN + 255) / 256, 256>>>();
    scatter_kernel<<<(EE / 2 + 255) / 256, 256>>>(ei);
    attn_kernel<<<(NN * 32) / 256, 256>>>();
    out_kernel<<<(3125 + 3) / 4, 256>>>(Wo, bo, out);
}

// round 7
// speedup vs baseline: 2.0713x; 1.5146x over previous
#include <cuda_runtime.h>
#include <math.h>
#include <stdint.h>

#define NN 50000
#define EE 800000
#define INF_F 128
#define OUTF 64
#define HH 4
#define DD 16

#define QKV_BLOCKS 782          // ceil(50000/64)
#define QKV_SMEM  (98304 + 32768)

// ---------------- device scratch (no allocations allowed) ----------------
// Invariants maintained ACROSS calls (restored within each call):
//   g_cnt[] == 0  (zero-init at load; alloc_kernel re-zeroes after reading)
//   g_total == 0  (zero-init at load; scatter_kernel resets)
__device__ float g_q[NN * OUTF];
__device__ float g_k[NN * OUTF];
__device__ float g_v[NN * OUTF];
__device__ float g_att[NN * OUTF];
__device__ float g_qq[NN * HH];
__device__ float g_kk[NN * HH];
__device__ int   g_cnt[NN];
__device__ int   g_rs[NN];
__device__ int   g_cur[NN];
__device__ int   g_csr[EE];
__device__ int   g_is64;
__device__ int   g_total;

// packed f32x2 FMA: d = a*b + c elementwise on packed pairs (Blackwell FFMA2)
__device__ __forceinline__ unsigned long long ffma2(
    unsigned long long a, unsigned long long b, unsigned long long c)
{
    unsigned long long d;
    asm("fma.rn.f32x2 %0, %1, %2, %3;" : "=l"(d) : "l"(a), "l"(b), "l"(c));
    return d;
}

__device__ __forceinline__ float unpack_sum(unsigned long long a) {
    float lo = __uint_as_float((unsigned)(a & 0xffffffffu));
    float hi = __uint_as_float((unsigned)(a >> 32));
    return lo + hi;
}

// ---------------- fused QKV projection + edge histogram + self-products ---
// Register-tiled GEMM: 512 threads, 64-row tile. All of W (3x64x128 fp32)
// staged in smem transposed to [k4][sel*64+cc] (coalesced global reads,
// conflict-free smem reads: lanes walk cc at 16B stride). x tile staged as
// [row][k4] (warp-broadcast reads). Thread (cc, rg) computes 8 rows x 3 sels
// with 24 packed-FFMA2 accumulators -> FMA-pipe bound.
// Also: per-block edge_index dtype detect, 1024-edge histogram slice,
// Minkowski self-products for q,k.
__global__ __launch_bounds__(512) void qkv_kernel(
    const float* __restrict__ x,
    const float* __restrict__ Wq, const float* __restrict__ bq,
    const float* __restrict__ Wk, const float* __restrict__ bk,
    const float* __restrict__ Wv, const float* __restrict__ bv,
    const void* __restrict__ ei)
{
    extern __shared__ __align__(16) char smem[];
    float4* wsm = (float4*)smem;                       // [32][192] float4
    float4* xs4 = (float4*)(smem + 98304);             // [64][32]  float4
    __shared__ int s_is64;

    int tid = threadIdx.x;
    int tile = blockIdx.x;
    int row0 = tile * 64;

    // ---- dtype detection (int64 vs int32: int32 read as int64 packs two
    // indices into one word -> out-of-range w.h.p. over 1024 words) ----
    if (tid < 32) {
        const long long* e64 = (const long long*)ei;
        int ok = 1;
        for (int t = tid; t < 1024; t += 32) {
            long long v = e64[t];
            if (v < 0 || v >= NN) ok = 0;
        }
        unsigned b = __ballot_sync(0xffffffffu, ok);
        if (tid == 0) {
            int f = (b == 0xffffffffu) ? 1 : 0;
            s_is64 = f;
            if (tile == 0) g_is64 = f;
        }
    }

    // ---- stage W transposed: wsm[k4*192 + sel*64 + cc] = W_sel[cc][4k4..] ----
    {
        const float4* Wsrc0 = (const float4*)Wq;
        const float4* Wsrc1 = (const float4*)Wk;
        const float4* Wsrc2 = (const float4*)Wv;
#pragma unroll
        for (int i = tid; i < 2048; i += 512) {
            int ccw = i >> 5, k4 = i & 31;
            wsm[k4 * 192 +       ccw] = Wsrc0[ccw * 32 + k4];
            wsm[k4 * 192 +  64 + ccw] = Wsrc1[ccw * 32 + k4];
            wsm[k4 * 192 + 128 + ccw] = Wsrc2[ccw * 32 + k4];
        }
    }

    // ---- stage x tile [64][128], zero-padded past NN ----
    {
        const float4* xg4 = (const float4*)(x + (size_t)row0 * 128);
#pragma unroll
        for (int i = tid; i < 2048; i += 512) {
            int row = i >> 5;
            float4 vz = make_float4(0.f, 0.f, 0.f, 0.f);
            if (row0 + row < NN) vz = xg4[i];
            xs4[i] = vz;
        }
    }
    __syncthreads();

    // ---- fused histogram: this block's 1024 edges (g_cnt starts all-zero) ----
    {
        int is64 = s_is64;
#pragma unroll
        for (int u = 0; u < 2; u++) {
            long long e = (long long)tile * 1024 + u * 512 + tid;
            if (e < EE) {
                int dst = is64 ? (int)((const long long*)ei)[EE + e]
                               : ((const int*)ei)[EE + e];
                atomicAdd(&g_cnt[dst], 1);
            }
        }
    }

    int cc = tid & 63;
    int rg = tid >> 6;     // 0..7 -> rows rg*8 .. rg*8+7

    unsigned long long aq[8], ak[8], av[8];
#pragma unroll
    for (int r = 0; r < 8; r++) { aq[r] = 0ull; ak[r] = 0ull; av[r] = 0ull; }

    const ulonglong2* ws2 = (const ulonglong2*)smem;
    const ulonglong2* xs2 = (const ulonglong2*)xs4;
    int xbase = rg * 8 * 32;

#pragma unroll 4
    for (int k4 = 0; k4 < 32; k4++) {
        ulonglong2 wqv = ws2[k4 * 192 +       cc];
        ulonglong2 wkv = ws2[k4 * 192 +  64 + cc];
        ulonglong2 wvv = ws2[k4 * 192 + 128 + cc];
#pragma unroll
        for (int r = 0; r < 8; r++) {
            ulonglong2 xv = xs2[xbase + r * 32 + k4];
            aq[r] = ffma2(wqv.x, xv.x, aq[r]);
            aq[r] = ffma2(wqv.y, xv.y, aq[r]);
            ak[r] = ffma2(wkv.x, xv.x, ak[r]);
            ak[r] = ffma2(wkv.y, xv.y, ak[r]);
            av[r] = ffma2(wvv.x, xv.x, av[r]);
            av[r] = ffma2(wvv.y, xv.y, av[r]);
        }
    }

    float bqv = bq[cc], bkv = bk[cc], bvv = bv[cc];
    float rq[8], rk[8];
    int rbase = row0 + rg * 8;
#pragma unroll
    for (int r = 0; r < 8; r++) {
        float vq = unpack_sum(aq[r]) + bqv;
        float vk = unpack_sum(ak[r]) + bkv;
        float vv = unpack_sum(av[r]) + bvv;
        rq[r] = vq; rk[r] = vk;
        int row = rbase + r;
        if (row < NN) {
            g_q[row * 64 + cc] = vq;
            g_k[row * 64 + cc] = vk;
            g_v[row * 64 + cc] = vv;
        }
    }

    // Minkowski self-products: reduce res^2*sign over the 16 lanes of each
    // head (warp = 32 consecutive cc -> two heads per warp)
    {
        float sign = ((cc & 15) == 15) ? -1.f : 1.f;
        int h = cc >> 4;
#pragma unroll
        for (int r = 0; r < 8; r++) {
            float pq = rq[r] * rq[r] * sign;
            float pk = rk[r] * rk[r] * sign;
            pq += __shfl_xor_sync(0xffffffffu, pq, 1);
            pk += __shfl_xor_sync(0xffffffffu, pk, 1);
            pq += __shfl_xor_sync(0xffffffffu, pq, 2);
            pk += __shfl_xor_sync(0xffffffffu, pk, 2);
            pq += __shfl_xor_sync(0xffffffffu, pq, 4);
            pk += __shfl_xor_sync(0xffffffffu, pk, 4);
            pq += __shfl_xor_sync(0xffffffffu, pq, 8);
            pk += __shfl_xor_sync(0xffffffffu, pk, 8);
            int row = rbase + r;
            if ((cc & 15) == 0 && row < NN) {
                g_qq[row * 4 + h] = pq;
                g_kk[row * 4 + h] = pk;
            }
        }
    }
}

// range allocation: order-free replacement for a prefix scan. Each node gets
// a contiguous chunk [off, off+cnt) via one aggregated atomic (REDUX.SUM).
// Re-zeroes g_cnt after reading (restores the cross-call invariant).
__global__ void alloc_kernel() {
    int i = blockIdx.x * blockDim.x + threadIdx.x;
    if (i >= NN) return;
    int c = g_cnt[i];
    g_cnt[i] = 0;
    int off = atomicAdd(&g_total, c);
    g_rs[i] = off;
    g_cur[i] = off;
}

// scatter: 2 edges per thread, vectorized index loads. Resets g_total.
__global__ void scatter_kernel(const void* ei) {
    int is64 = g_is64;
    int t = blockIdx.x * blockDim.x + threadIdx.x;
    if (t == 0) g_total = 0;
    if (t >= EE / 2) return;
    int s0, s1, d0, d1;
    if (is64) {
        const long long* e = (const long long*)ei;
        longlong2 sv = ((const longlong2*)e)[t];
        longlong2 dv = ((const longlong2*)(e + EE))[t];
        s0 = (int)sv.x; s1 = (int)sv.y;
        d0 = (int)dv.x; d1 = (int)dv.y;
    } else {
        const int* e = (const int*)ei;
        int2 sv = ((const int2*)e)[t];
        int2 dv = ((const int2*)(e + EE))[t];
        s0 = sv.x; s1 = sv.y;
        d0 = dv.x; d1 = dv.y;
    }
    g_csr[atomicAdd(&g_cur[d0], 1)] = s0;
    g_csr[atomicAdd(&g_cur[d1], 1)] = s1;
}

// ---------------- gather attention: one warp per dst node --------------------
// lane l owns flat dims {2l, 2l+1}; head h = l/8; 8-lane groups reduce dots.
// After scatter, g_cur[i] == row_end, so [g_rs[i], g_cur[i]) is the edge range.
// exp(-acosh(arg)) == 1/(arg + sqrt(arg^2-1))  -> no MUFU log/exp.
// Softmax denom cancels exactly into the L2 norm: att = S / (||S|| + EPS*s),
// and the max-shift cancels too (scale invariance), so no online max needed.
__global__ __launch_bounds__(256) void attn_kernel() {
    int gtid = blockIdx.x * blockDim.x + threadIdx.x;
    int i = gtid >> 5;
    if (i >= NN) return;
    int lane = threadIdx.x & 31;
    int h  = lane >> 3;
    int dp = lane & 7;

    float2 kv = *(const float2*)(g_k + i * 64 + 2 * lane);
    float sign = (dp == 7) ? -1.f : 1.f;   // flat dim 15 carries Minkowski minus
    float kkv = g_kk[i * 4 + h];

    int js = g_rs[i];
    int je = g_cur[i];

    float s = 0.f, a0 = 0.f, a1 = 0.f;
    const float CLMP = (1.0f + 1e-6f) * (1.0f + 1e-6f);

    int j = js;
    for (; j + 3 < je; j += 4) {
        int s0 = g_csr[j];
        int s1 = g_csr[j + 1];
        int s2 = g_csr[j + 2];
        int s3 = g_csr[j + 3];
        float2 q0 = *(const float2*)(g_q + s0 * 64 + 2 * lane);
        float2 q1 = *(const float2*)(g_q + s1 * 64 + 2 * lane);
        float2 q2 = *(const float2*)(g_q + s2 * 64 + 2 * lane);
        float2 q3 = *(const float2*)(g_q + s3 * 64 + 2 * lane);
        float2 v0 = *(const float2*)(g_v + s0 * 64 + 2 * lane);
        float2 v1 = *(const float2*)(g_v + s1 * 64 + 2 * lane);
        float2 v2 = *(const float2*)(g_v + s2 * 64 + 2 * lane);
        float2 v3 = *(const float2*)(g_v + s3 * 64 + 2 * lane);
        float qq0 = g_qq[s0 * 4 + h];
        float qq1 = g_qq[s1 * 4 + h];
        float qq2 = g_qq[s2 * 4 + h];
        float qq3 = g_qq[s3 * 4 + h];

        float d0 = fmaf(q0.x, kv.x, sign * q0.y * kv.y);
        float d1 = fmaf(q1.x, kv.x, sign * q1.y * kv.y);
        float d2 = fmaf(q2.x, kv.x, sign * q2.y * kv.y);
        float d3 = fmaf(q3.x, kv.x, sign * q3.y * kv.y);
#pragma unroll
        for (int o = 1; o <= 4; o <<= 1) {
            d0 += __shfl_xor_sync(0xffffffffu, d0, o);
            d1 += __shfl_xor_sync(0xffffffffu, d1, o);
            d2 += __shfl_xor_sync(0xffffffffu, d2, o);
            d3 += __shfl_xor_sync(0xffffffffu, d3, o);
        }

        float r0 = __fdividef(d0 * d0, fmaxf(fabsf(qq0 * kkv), 1e-9f)) + 1e-9f;
        float r1 = __fdividef(d1 * d1, fmaxf(fabsf(qq1 * kkv), 1e-9f)) + 1e-9f;
        float r2 = __fdividef(d2 * d2, fmaxf(fabsf(qq2 * kkv), 1e-9f)) + 1e-9f;
        float r3 = __fdividef(d3 * d3, fmaxf(fabsf(qq3 * kkv), 1e-9f)) + 1e-9f;
        r0 = fmaxf(r0, CLMP);
        r1 = fmaxf(r1, CLMP);
        r2 = fmaxf(r2, CLMP);
        r3 = fmaxf(r3, CLMP);
        float p0 = __frcp_rn(sqrtf(r0) + sqrtf(r0 - 1.0f));
        float p1 = __frcp_rn(sqrtf(r1) + sqrtf(r1 - 1.0f));
        float p2 = __frcp_rn(sqrtf(r2) + sqrtf(r2 - 1.0f));
        float p3 = __frcp_rn(sqrtf(r3) + sqrtf(r3 - 1.0f));

        s += (p0 + p1) + (p2 + p3);
        a0 = fmaf(p0, v0.x, fmaf(p1, v1.x, fmaf(p2, v2.x, fmaf(p3, v3.x, a0))));
        a1 = fmaf(p0, v0.y, fmaf(p1, v1.y, fmaf(p2, v2.y, fmaf(p3, v3.y, a1))));
    }
    for (; j < je; j++) {
        int s0 = g_csr[j];
        float2 q0 = *(const float2*)(g_q + s0 * 64 + 2 * lane);
        float2 v0 = *(const float2*)(g_v + s0 * 64 + 2 * lane);
        float qq0 = g_qq[s0 * 4 + h];
        float d0 = fmaf(q0.x, kv.x, sign * q0.y * kv.y);
        d0 += __shfl_xor_sync(0xffffffffu, d0, 1);
        d0 += __shfl_xor_sync(0xffffffffu, d0, 2);
        d0 += __shfl_xor_sync(0xffffffffu, d0, 4);
        float r0 = __fdividef(d0 * d0, fmaxf(fabsf(qq0 * kkv), 1e-9f)) + 1e-9f;
        r0 = fmaxf(r0, CLMP);
        float p0 = __frcp_rn(sqrtf(r0) + sqrtf(r0 - 1.0f));
        s += p0;
        a0 = fmaf(p0, v0.x, a0);
        a1 = fmaf(p0, v0.y, a1);
    }

    float nsq = fmaf(a0, a0, a1 * a1);
    nsq += __shfl_xor_sync(0xffffffffu, nsq, 1);
    nsq += __shfl_xor_sync(0xffffffffu, nsq, 2);
    nsq += __shfl_xor_sync(0xffffffffu, nsq, 4);
    float norm = sqrtf(nsq);
    // agg = S/s, attended = agg/(||agg||+EPS) = S/(||S|| + EPS*s); 0 if no mass
    float scale = (norm > 0.f) ? __frcp_rn(norm + 1e-9f * s) : 0.f;
    float2 o;
    o.x = a0 * scale;
    o.y = a1 * scale;
    *(float2*)(g_att + i * 64 + 2 * lane) = o;
}

// ---------------- output projection: [N,64] x [64,64]^T + bias --------------
// 256-thread blocks = 4 independent 16-row tiles (64 columns each), FFMA2.
// Wo read is amortized over 16 rows per tile (per-node Wo reads were the
// R4/R5 regression).
__global__ __launch_bounds__(256) void out_kernel(
    const float* __restrict__ Wo, const float* __restrict__ bo,
    float* __restrict__ out)
{
    __shared__ __align__(16) float as[4][16 * 64];
    int grp = threadIdx.x >> 6;     // tile within block
    int tid = threadIdx.x & 63;     // column
    int tile = blockIdx.x * 4 + grp;
    if (tile >= 3125) return;       // 3125 tiles * 16 rows = 50000

    const float4* ag = (const float4*)(g_att + (size_t)tile * 16 * 64);
    float4* as4 = (float4*)as[grp];
    for (int i = tid; i < 256; i += 64) as4[i] = ag[i];
    __syncthreads();

    unsigned long long acc[16];
#pragma unroll
    for (int r = 0; r < 16; r++) acc[r] = 0ull;

    const ulonglong2* Wr = (const ulonglong2*)(Wo + tid * 64);
    const ulonglong2* as2 = (const ulonglong2*)as[grp];
#pragma unroll 4
    for (int k4 = 0; k4 < 16; k4++) {
        ulonglong2 w = Wr[k4];
#pragma unroll
        for (int r = 0; r < 16; r++) {
            ulonglong2 a = as2[r * 16 + k4];
            acc[r] = ffma2(w.x, a.x, acc[r]);
            acc[r] = ffma2(w.y, a.y, acc[r]);
        }
    }

    float b = bo[tid];
    int row0 = tile * 16;
#pragma unroll
    for (int r = 0; r < 16; r++) out[(row0 + r) * 64 + tid] = unpack_sum(acc[r]) + b;
}

// ---------------- launch (single stream, 5 kernels) --------------------------
extern "C" void kernel_launch(void* const* d_in, const int* in_sizes, int n_in,
                              void* d_out, int out_size) {
    const float* x  = (const float*)d_in[0];
    const void*  ei = d_in[1];
    const float* Wq = (const float*)d_in[2];
    const float* bq = (const float*)d_in[3];
    const float* Wk = (const float*)d_in[4];
    const float* bk = (const float*)d_in[5];
    const float* Wv = (const float*)d_in[6];
    const float* bv = (const float*)d_in[7];
    const float* Wo = (const float*)d_in[8];
    const float* bo = (const float*)d_in[9];
    float* out = (float*)d_out;

    cudaFuncSetAttribute(qkv_kernel,
                         cudaFuncAttributeMaxDynamicSharedMemorySize, QKV_SMEM);

    qkv_kernel<<<QKV_BLOCKS, 512, QKV_SMEM>>>(x, Wq, bq, Wk, bk, Wv, bv, ei);
    alloc_kernel<<<(NN + 255) / 256, 256>>>();
    scatter_kernel<<<(EE / 2 + 255) / 256, 256>>>(ei);
    attn_kernel<<<(NN * 32) / 256, 256>>>();
    out_kernel<<<(3125 + 3) / 4, 256>>>(Wo, bo, out);
}

// round 8
// speedup vs baseline: 2.1198x; 1.0234x over previous
#include <cuda_runtime.h>
#include <math.h>
#include <stdint.h>

#define NN 50000
#define EE 800000
#define INF_F 128
#define OUTF 64
#define HH 4
#define DD 16

#define QKV_BLOCKS 782          // ceil(50000/64)
#define QKV_SMEM  (98304 + 32768)

// ---------------- device scratch (no allocations allowed) ----------------
// Invariants maintained ACROSS calls (restored within each call):
//   g_cnt[] == 0  (zero-init at load; alloc_kernel re-zeroes after reading)
//   g_total == 0  (zero-init at load; scatter_kernel resets)
__device__ float g_q[NN * OUTF];
__device__ float g_k[NN * OUTF];
__device__ float g_v[NN * OUTF];
__device__ float g_att[NN * OUTF];
__device__ float g_qq[NN * HH];
__device__ float g_kk[NN * HH];
__device__ int   g_cnt[NN];
__device__ int   g_rs[NN];
__device__ int   g_cur[NN];
__device__ int   g_csr[EE];
__device__ int   g_is64;
__device__ int   g_total;

// packed f32x2 FMA: d = a*b + c elementwise on packed pairs (Blackwell FFMA2)
__device__ __forceinline__ unsigned long long ffma2(
    unsigned long long a, unsigned long long b, unsigned long long c)
{
    unsigned long long d;
    asm("fma.rn.f32x2 %0, %1, %2, %3;" : "=l"(d) : "l"(a), "l"(b), "l"(c));
    return d;
}

__device__ __forceinline__ float unpack_sum(unsigned long long a) {
    float lo = __uint_as_float((unsigned)(a & 0xffffffffu));
    float hi = __uint_as_float((unsigned)(a >> 32));
    return lo + hi;
}

__device__ __forceinline__ unsigned long long pack2(float a, float b) {
    return (unsigned long long)__float_as_uint(a)
         | ((unsigned long long)__float_as_uint(b) << 32);
}

// ---------------- fused QKV projection + edge histogram + self-products ---
// Register-tiled GEMM: 512 threads, 64-row tile. All of W (3x64x128 fp32)
// staged in smem transposed to [k4][sel*64+cc] (coalesced global reads,
// conflict-free smem reads). x tile staged as [row][k4] (broadcast reads).
// Thread (cc, rg) computes 8 rows x 3 sels with 24 packed-FFMA2 accumulators.
// Also: per-block edge_index dtype detect, 1024-edge histogram slice,
// Minkowski self-products for q,k.
__global__ __launch_bounds__(512) void qkv_kernel(
    const float* __restrict__ x,
    const float* __restrict__ Wq, const float* __restrict__ bq,
    const float* __restrict__ Wk, const float* __restrict__ bk,
    const float* __restrict__ Wv, const float* __restrict__ bv,
    const void* __restrict__ ei)
{
    extern __shared__ __align__(16) char smem[];
    float4* wsm = (float4*)smem;                       // [32][192] float4
    float4* xs4 = (float4*)(smem + 98304);             // [64][32]  float4
    __shared__ int s_is64;

    int tid = threadIdx.x;
    int tile = blockIdx.x;
    int row0 = tile * 64;

    // ---- dtype detection (int64 vs int32: int32 read as int64 packs two
    // indices into one word -> out-of-range w.h.p. over 1024 words) ----
    if (tid < 32) {
        const long long* e64 = (const long long*)ei;
        int ok = 1;
        for (int t = tid; t < 1024; t += 32) {
            long long v = e64[t];
            if (v < 0 || v >= NN) ok = 0;
        }
        unsigned b = __ballot_sync(0xffffffffu, ok);
        if (tid == 0) {
            int f = (b == 0xffffffffu) ? 1 : 0;
            s_is64 = f;
            if (tile == 0) g_is64 = f;
        }
    }

    // ---- stage W transposed: wsm[k4*192 + sel*64 + cc] = W_sel[cc][4k4..] ----
    {
        const float4* Wsrc0 = (const float4*)Wq;
        const float4* Wsrc1 = (const float4*)Wk;
        const float4* Wsrc2 = (const float4*)Wv;
#pragma unroll
        for (int i = tid; i < 2048; i += 512) {
            int ccw = i >> 5, k4 = i & 31;
            wsm[k4 * 192 +       ccw] = Wsrc0[ccw * 32 + k4];
            wsm[k4 * 192 +  64 + ccw] = Wsrc1[ccw * 32 + k4];
            wsm[k4 * 192 + 128 + ccw] = Wsrc2[ccw * 32 + k4];
        }
    }

    // ---- stage x tile [64][128], zero-padded past NN ----
    {
        const float4* xg4 = (const float4*)(x + (size_t)row0 * 128);
#pragma unroll
        for (int i = tid; i < 2048; i += 512) {
            int row = i >> 5;
            float4 vz = make_float4(0.f, 0.f, 0.f, 0.f);
            if (row0 + row < NN) vz = xg4[i];
            xs4[i] = vz;
        }
    }
    __syncthreads();

    // ---- fused histogram: this block's 1024 edges (g_cnt starts all-zero) ----
    {
        int is64 = s_is64;
#pragma unroll
        for (int u = 0; u < 2; u++) {
            long long e = (long long)tile * 1024 + u * 512 + tid;
            if (e < EE) {
                int dst = is64 ? (int)((const long long*)ei)[EE + e]
                               : ((const int*)ei)[EE + e];
                atomicAdd(&g_cnt[dst], 1);
            }
        }
    }

    int cc = tid & 63;
    int rg = tid >> 6;     // 0..7 -> rows rg*8 .. rg*8+7

    unsigned long long aq[8], ak[8], av[8];
#pragma unroll
    for (int r = 0; r < 8; r++) { aq[r] = 0ull; ak[r] = 0ull; av[r] = 0ull; }

    const ulonglong2* ws2 = (const ulonglong2*)smem;
    const ulonglong2* xs2 = (const ulonglong2*)xs4;
    int xbase = rg * 8 * 32;

#pragma unroll 4
    for (int k4 = 0; k4 < 32; k4++) {
        ulonglong2 wqv = ws2[k4 * 192 +       cc];
        ulonglong2 wkv = ws2[k4 * 192 +  64 + cc];
        ulonglong2 wvv = ws2[k4 * 192 + 128 + cc];
#pragma unroll
        for (int r = 0; r < 8; r++) {
            ulonglong2 xv = xs2[xbase + r * 32 + k4];
            aq[r] = ffma2(wqv.x, xv.x, aq[r]);
            aq[r] = ffma2(wqv.y, xv.y, aq[r]);
            ak[r] = ffma2(wkv.x, xv.x, ak[r]);
            ak[r] = ffma2(wkv.y, xv.y, ak[r]);
            av[r] = ffma2(wvv.x, xv.x, av[r]);
            av[r] = ffma2(wvv.y, xv.y, av[r]);
        }
    }

    float bqv = bq[cc], bkv = bk[cc], bvv = bv[cc];
    float rq[8], rk[8];
    int rbase = row0 + rg * 8;
#pragma unroll
    for (int r = 0; r < 8; r++) {
        float vq = unpack_sum(aq[r]) + bqv;
        float vk = unpack_sum(ak[r]) + bkv;
        float vv = unpack_sum(av[r]) + bvv;
        rq[r] = vq; rk[r] = vk;
        int row = rbase + r;
        if (row < NN) {
            g_q[row * 64 + cc] = vq;
            g_k[row * 64 + cc] = vk;
            g_v[row * 64 + cc] = vv;
        }
    }

    // Minkowski self-products: reduce res^2*sign over the 16 lanes of each
    // head (warp = 32 consecutive cc -> two heads per warp)
    {
        float sign = ((cc & 15) == 15) ? -1.f : 1.f;
        int h = cc >> 4;
#pragma unroll
        for (int r = 0; r < 8; r++) {
            float pq = rq[r] * rq[r] * sign;
            float pk = rk[r] * rk[r] * sign;
            pq += __shfl_xor_sync(0xffffffffu, pq, 1);
            pk += __shfl_xor_sync(0xffffffffu, pk, 1);
            pq += __shfl_xor_sync(0xffffffffu, pq, 2);
            pk += __shfl_xor_sync(0xffffffffu, pk, 2);
            pq += __shfl_xor_sync(0xffffffffu, pq, 4);
            pk += __shfl_xor_sync(0xffffffffu, pk, 4);
            pq += __shfl_xor_sync(0xffffffffu, pq, 8);
            pk += __shfl_xor_sync(0xffffffffu, pk, 8);
            int row = rbase + r;
            if ((cc & 15) == 0 && row < NN) {
                g_qq[row * 4 + h] = pq;
                g_kk[row * 4 + h] = pk;
            }
        }
    }
}

// range allocation: order-free replacement for a prefix scan. Each node gets
// a contiguous chunk [off, off+cnt) via one aggregated atomic (REDUX.SUM).
// Re-zeroes g_cnt after reading (restores the cross-call invariant).
__global__ void alloc_kernel() {
    int i = blockIdx.x * blockDim.x + threadIdx.x;
    if (i >= NN) return;
    int c = g_cnt[i];
    g_cnt[i] = 0;
    int off = atomicAdd(&g_total, c);
    g_rs[i] = off;
    g_cur[i] = off;
}

// scatter: 2 edges per thread, vectorized index loads. Resets g_total.
__global__ void scatter_kernel(const void* ei) {
    int is64 = g_is64;
    int t = blockIdx.x * blockDim.x + threadIdx.x;
    if (t == 0) g_total = 0;
    if (t >= EE / 2) return;
    int s0, s1, d0, d1;
    if (is64) {
        const long long* e = (const long long*)ei;
        longlong2 sv = ((const longlong2*)e)[t];
        longlong2 dv = ((const longlong2*)(e + EE))[t];
        s0 = (int)sv.x; s1 = (int)sv.y;
        d0 = (int)dv.x; d1 = (int)dv.y;
    } else {
        const int* e = (const int*)ei;
        int2 sv = ((const int2*)e)[t];
        int2 dv = ((const int2*)(e + EE))[t];
        s0 = sv.x; s1 = sv.y;
        d0 = dv.x; d1 = dv.y;
    }
    g_csr[atomicAdd(&g_cur[d0], 1)] = s0;
    g_csr[atomicAdd(&g_cur[d1], 1)] = s1;
}

// ---------------- gather attention: lane-per-(edge,head) ---------------------
// One warp per dst node, 8 edges per iteration. Dot role: lane l handles edge
// e=l>>2, head h'=l&3 -> full 16-dim Minkowski dot computed IN-LANE via 8
// FFMA2 against the k head held in registers (dim 15 pre-negated). Score math
// computed once per (edge,head) -- no warp-wide duplication, no dot shfls.
// Agg role: lane l owns flat dims {2l,2l+1} (head h=l>>3); per edge, src index
// and weight arrive via 2 shfl broadcasts.
// exp(-acosh(arg)) == 1/(arg + sqrt(arg^2-1))  -> no MUFU log/exp.
// Softmax denom cancels exactly into the L2 norm: att = S / (||S|| + EPS*s).
__global__ __launch_bounds__(256) void attn_kernel() {
    int gtid = blockIdx.x * blockDim.x + threadIdx.x;
    int i = gtid >> 5;
    if (i >= NN) return;
    int lane = threadIdx.x & 31;
    int hp = lane & 3;      // dot-role head
    int er = lane >> 2;     // dot-role edge slot (0..7)
    int h  = lane >> 3;     // agg-role head

    // k head h' packed into 8 f32x2 registers, dim 15 negated (Minkowski)
    unsigned long long kd[8];
    {
        const float4* kp = (const float4*)(g_k + i * 64 + hp * 16);
        float4 k0 = kp[0], k1 = kp[1], k2 = kp[2], k3 = kp[3];
        k3.w = -k3.w;
        kd[0] = pack2(k0.x, k0.y); kd[1] = pack2(k0.z, k0.w);
        kd[2] = pack2(k1.x, k1.y); kd[3] = pack2(k1.z, k1.w);
        kd[4] = pack2(k2.x, k2.y); kd[5] = pack2(k2.z, k2.w);
        kd[6] = pack2(k3.x, k3.y); kd[7] = pack2(k3.z, k3.w);
    }
    float kkv = g_kk[i * 4 + hp];

    int js = g_rs[i];
    int je = g_cur[i];

    float s = 0.f, a0 = 0.f, a1 = 0.f;
    const float CLMP = (1.0f + 1e-6f) * (1.0f + 1e-6f);

    for (int j = js; j < je; j += 8) {
        int pos = j + er;
        int valid = pos < je;
        int src = valid ? g_csr[pos] : 0;

        // in-lane 16-dim Minkowski dot (two chains for ILP)
        const ulonglong2* qp = (const ulonglong2*)(g_q + src * 64 + hp * 16);
        ulonglong2 qa = qp[0], qb = qp[1], qc = qp[2], qd = qp[3];
        unsigned long long accA = 0ull, accB = 0ull;
        accA = ffma2(qa.x, kd[0], accA);
        accB = ffma2(qa.y, kd[1], accB);
        accA = ffma2(qb.x, kd[2], accA);
        accB = ffma2(qb.y, kd[3], accB);
        accA = ffma2(qc.x, kd[4], accA);
        accB = ffma2(qc.y, kd[5], accB);
        accA = ffma2(qd.x, kd[6], accA);
        accB = ffma2(qd.y, kd[7], accB);
        float d = unpack_sum(accA) + unpack_sum(accB);

        float qq = g_qq[src * 4 + hp];
        float r = __fdividef(d * d, fmaxf(fabsf(qq * kkv), 1e-9f)) + 1e-9f;
        r = fmaxf(r, CLMP);
        float p = __frcp_rn(sqrtf(r) + sqrtf(r - 1.0f));
        if (!valid) p = 0.f;

        // aggregation: dims {2*lane, 2*lane+1}, head h = lane>>3
#pragma unroll
        for (int e = 0; e < 8; e++) {
            int   sr = __shfl_sync(0xffffffffu, src, e * 4);
            float pw = __shfl_sync(0xffffffffu, p,   e * 4 + h);
            float2 vv = *(const float2*)(g_v + sr * 64 + 2 * lane);
            a0 = fmaf(pw, vv.x, a0);
            a1 = fmaf(pw, vv.y, a1);
            s += pw;
        }
    }

    float nsq = fmaf(a0, a0, a1 * a1);
    nsq += __shfl_xor_sync(0xffffffffu, nsq, 1);
    nsq += __shfl_xor_sync(0xffffffffu, nsq, 2);
    nsq += __shfl_xor_sync(0xffffffffu, nsq, 4);
    float norm = sqrtf(nsq);
    // agg = S/s, attended = agg/(||agg||+EPS) = S/(||S|| + EPS*s); 0 if no mass
    float scale = (norm > 0.f) ? __frcp_rn(norm + 1e-9f * s) : 0.f;
    float2 o;
    o.x = a0 * scale;
    o.y = a1 * scale;
    *(float2*)(g_att + i * 64 + 2 * lane) = o;
}

// ---------------- output projection: [N,64] x [64,64]^T + bias --------------
// 256-thread blocks = 4 independent 16-row tiles (64 columns each), FFMA2.
// Wo read is amortized over 16 rows per tile (per-node Wo reads were the
// R4/R5 regression).
__global__ __launch_bounds__(256) void out_kernel(
    const float* __restrict__ Wo, const float* __restrict__ bo,
    float* __restrict__ out)
{
    __shared__ __align__(16) float as[4][16 * 64];
    int grp = threadIdx.x >> 6;     // tile within block
    int tid = threadIdx.x & 63;     // column
    int tile = blockIdx.x * 4 + grp;
    if (tile >= 3125) return;       // 3125 tiles * 16 rows = 50000

    const float4* ag = (const float4*)(g_att + (size_t)tile * 16 * 64);
    float4* as4 = (float4*)as[grp];
    for (int i = tid; i < 256; i += 64) as4[i] = ag[i];
    __syncthreads();

    unsigned long long acc[16];
#pragma unroll
    for (int r = 0; r < 16; r++) acc[r] = 0ull;

    const ulonglong2* Wr = (const ulonglong2*)(Wo + tid * 64);
    const ulonglong2* as2 = (const ulonglong2*)as[grp];
#pragma unroll 4
    for (int k4 = 0; k4 < 16; k4++) {
        ulonglong2 w = Wr[k4];
#pragma unroll
        for (int r = 0; r < 16; r++) {
            ulonglong2 a = as2[r * 16 + k4];
            acc[r] = ffma2(w.x, a.x, acc[r]);
            acc[r] = ffma2(w.y, a.y, acc[r]);
        }
    }

    float b = bo[tid];
    int row0 = tile * 16;
#pragma unroll
    for (int r = 0; r < 16; r++) out[(row0 + r) * 64 + tid] = unpack_sum(acc[r]) + b;
}

// ---------------- launch (single stream, 5 kernels) --------------------------
extern "C" void kernel_launch(void* const* d_in, const int* in_sizes, int n_in,
                              void* d_out, int out_size) {
    const float* x  = (const float*)d_in[0];
    const void*  ei = d_in[1];
    const float* Wq = (const float*)d_in[2];
    const float* bq = (const float*)d_in[3];
    const float* Wk = (const float*)d_in[4];
    const float* bk = (const float*)d_in[5];
    const float* Wv = (const float*)d_in[6];
    const float* bv = (const float*)d_in[7];
    const float* Wo = (const float*)d_in[8];
    const float* bo = (const float*)d_in[9];
    float* out = (float*)d_out;

    cudaFuncSetAttribute(qkv_kernel,
                         cudaFuncAttributeMaxDynamicSharedMemorySize, QKV_SMEM);

    qkv_kernel<<<QKV_BLOCKS, 512, QKV_SMEM>>>(x, Wq, bq, Wk, bk, Wv, bv, ei);
    alloc_kernel<<<(NN + 255) / 256, 256>>>();
    scatter_kernel<<<(EE / 2 + 255) / 256, 256>>>(ei);
    attn_kernel<<<(NN * 32) / 256, 256>>>();
    out_kernel<<<(3125 + 3) / 4, 256>>>(Wo, bo, out);
}